// round 7
// baseline (speedup 1.0000x reference)
#include <cuda_runtime.h>

#define Cdim 768
#define CRdim 192
#define Bb 8
#define Nn 1024
#define G 128
#define NT 192

// Per-call accumulators (zeroed in phase 1 every call) and gc partials
// (fully overwritten every call) — no cross-call state.
#define S_VB 0
#define S_CA (Bb * Cdim)
#define S_YB (2 * Bb * Cdim)
#define S_H  (3 * Bb * Cdim)
#define S_ACC_N (3 * Bb * Cdim + Bb * CRdim)
__device__ __align__(16) float g_acc[S_ACC_N];
__device__ __align__(16) float g_part[G * Cdim];
__device__ unsigned int g_cnt;
__device__ volatile unsigned int g_sense;

// Sense-reversing grid barrier: self-resetting (cnt returns to 0, sense
// toggles), so it is correct and identical-work on every call.
__device__ __forceinline__ void gbar() {
    __syncthreads();
    if (threadIdx.x == 0) {
        unsigned s = g_sense;
        __threadfence();
        if (atomicAdd(&g_cnt, 1u) == G - 1) {
            g_cnt = 0u;
            __threadfence();
            g_sense = s ^ 1u;
        } else {
            while (g_sense == s) __nanosleep(64);
        }
        __threadfence();
    }
    __syncthreads();
}

__global__ void __launch_bounds__(NT) k_all(
    const float* __restrict__ x,
    const float* __restrict__ Wv, const float* __restrict__ W1,
    const float* __restrict__ W2, const float* __restrict__ Wo,
    const float* __restrict__ bv, const float* __restrict__ b1,
    const float* __restrict__ b2, const float* __restrict__ bo,
    const float* __restrict__ gamma, const float* __restrict__ beta,
    float* __restrict__ out)
{
    __shared__ float smem[3 * Cdim];          // 9 KB, reused across phases
    float (*sa)[64] = (float (*)[64])smem;    // 8x64 slice for GEMM stages
    int t = threadIdx.x, g = blockIdx.x;
    int q = t >> 2, kg = t & 3;

    // ───── Phase 1: zero accumulators + gc partial (64 rows per block) ─────
    {
        int zi = g * NT + t;
        if (zi < S_ACC_N) g_acc[zi] = 0.f;

        int b = g >> 4, chunk = g & 15;
        const float4* p = reinterpret_cast<const float4*>(x)
                        + (size_t)(b * Nn + chunk * 64) * (Cdim / 4) + t;
        float4 a0 = make_float4(0.f, 0.f, 0.f, 0.f);
        float4 a1 = make_float4(0.f, 0.f, 0.f, 0.f);
        #pragma unroll 4
        for (int n = 0; n < 64; n += 2) {
            float4 v0 = p[(size_t)n * (Cdim / 4)];
            float4 v1 = p[(size_t)(n + 1) * (Cdim / 4)];
            a0.x += v0.x; a0.y += v0.y; a0.z += v0.z; a0.w += v0.w;
            a1.x += v1.x; a1.y += v1.y; a1.z += v1.z; a1.w += v1.w;
        }
        const float inv = 1.0f / Nn;
        float4 s4;
        s4.x = (a0.x + a1.x) * inv; s4.y = (a0.y + a1.y) * inv;
        s4.z = (a0.z + a1.z) * inv; s4.w = (a0.w + a1.w) * inv;
        reinterpret_cast<float4*>(&g_part[(size_t)g * Cdim])[t] = s4;
    }

    gbar();

    // ───── Stage A (blocks 0..59): vbar = gc@Wv, h = gc@W1 (k-split) ───────
    if (g < 60) {
        int ct = g / 12;               // 0..4  col tile (48 quads)
        int kt = g % 12;               // 0..11 k tile (64)
        int k0 = kt * 64;
        for (int i = t; i < Bb * 64; i += NT) {
            int b = i >> 6, kk = i & 63;
            float s = 0.f;
            const float* pp = &g_part[(size_t)(b * 16) * Cdim + k0 + kk];
            #pragma unroll
            for (int ch = 0; ch < 16; ch++) s += pp[(size_t)ch * Cdim];
            sa[b][kk] = s;
        }
        __syncthreads();
        int Q = ct * 48 + q;           // 0..239
        float acc[Bb][4];
        #pragma unroll
        for (int b = 0; b < Bb; b++) { acc[b][0]=0.f; acc[b][1]=0.f; acc[b][2]=0.f; acc[b][3]=0.f; }
        if (Q < 192) {
            const float4* wp = (const float4*)Wv + (size_t)(k0 + kg * 16) * 192 + Q;
            #pragma unroll
            for (int kk = 0; kk < 16; kk++) {
                float4 w = wp[(size_t)kk * 192];
                int ki = kg * 16 + kk;
                #pragma unroll
                for (int b = 0; b < Bb; b++) {
                    float a = sa[b][ki];
                    acc[b][0] += a * w.x; acc[b][1] += a * w.y;
                    acc[b][2] += a * w.z; acc[b][3] += a * w.w;
                }
            }
        } else {
            const float4* wp = (const float4*)W1 + (size_t)(k0 + kg * 16) * 48 + (Q - 192);
            #pragma unroll
            for (int kk = 0; kk < 16; kk++) {
                float4 w = wp[(size_t)kk * 48];
                int ki = kg * 16 + kk;
                #pragma unroll
                for (int b = 0; b < Bb; b++) {
                    float a = sa[b][ki];
                    acc[b][0] += a * w.x; acc[b][1] += a * w.y;
                    acc[b][2] += a * w.z; acc[b][3] += a * w.w;
                }
            }
        }
        #pragma unroll
        for (int b = 0; b < Bb; b++)
            #pragma unroll
            for (int j = 0; j < 4; j++) {
                acc[b][j] += __shfl_xor_sync(0xffffffffu, acc[b][j], 1);
                acc[b][j] += __shfl_xor_sync(0xffffffffu, acc[b][j], 2);
            }
        if (kg == 0) {
            if (Q < 192) {
                #pragma unroll
                for (int b = 0; b < Bb; b++)
                    #pragma unroll
                    for (int j = 0; j < 4; j++)
                        atomicAdd(&g_acc[S_VB + b * Cdim + 4 * Q + j], acc[b][j]);
            } else {
                #pragma unroll
                for (int b = 0; b < Bb; b++)
                    #pragma unroll
                    for (int j = 0; j < 4; j++)
                        atomicAdd(&g_acc[S_H + b * CRdim + 4 * (Q - 192) + j], acc[b][j]);
            }
        }
    }

    gbar();

    // ───── Stage B (blocks 0..11): ca_pre = relu(h+b1)@W2 ──────────────────
    if (g < 12) {
        int ct = g & 3;                // 0..3
        int kt = g >> 2;               // 0..2
        int k0 = kt * 64;
        for (int i = t; i < Bb * 64; i += NT) {
            int b = i >> 6, kk = i & 63;
            float v = g_acc[S_H + b * CRdim + k0 + kk] + b1[k0 + kk];
            sa[b][kk] = v > 0.f ? v : 0.f;
        }
        __syncthreads();
        int Q = ct * 48 + q;
        float acc[Bb][4];
        #pragma unroll
        for (int b = 0; b < Bb; b++) { acc[b][0]=0.f; acc[b][1]=0.f; acc[b][2]=0.f; acc[b][3]=0.f; }
        const float4* wp = (const float4*)W2 + (size_t)(k0 + kg * 16) * 192 + Q;
        #pragma unroll
        for (int kk = 0; kk < 16; kk++) {
            float4 w = wp[(size_t)kk * 192];
            int ki = kg * 16 + kk;
            #pragma unroll
            for (int b = 0; b < Bb; b++) {
                float a = sa[b][ki];
                acc[b][0] += a * w.x; acc[b][1] += a * w.y;
                acc[b][2] += a * w.z; acc[b][3] += a * w.w;
            }
        }
        #pragma unroll
        for (int b = 0; b < Bb; b++)
            #pragma unroll
            for (int j = 0; j < 4; j++) {
                acc[b][j] += __shfl_xor_sync(0xffffffffu, acc[b][j], 1);
                acc[b][j] += __shfl_xor_sync(0xffffffffu, acc[b][j], 2);
            }
        if (kg == 0) {
            #pragma unroll
            for (int b = 0; b < Bb; b++)
                #pragma unroll
                for (int j = 0; j < 4; j++)
                    atomicAdd(&g_acc[S_CA + b * Cdim + 4 * Q + j], acc[b][j]);
        }
    }

    gbar();

    // ───── Stage C (blocks 0..47): ybar = ((vbar+bv)*sigmoid(ca+b2))@Wo ────
    if (g < 48) {
        int ct = g & 3;                // 0..3
        int kt = g >> 2;               // 0..11
        int k0 = kt * 64;
        for (int i = t; i < Bb * 64; i += NT) {
            int b = i >> 6, kk = i & 63;
            int k = k0 + kk;
            float vb = g_acc[S_VB + b * Cdim + k] + bv[k];
            float cp = g_acc[S_CA + b * Cdim + k] + b2[k];
            sa[b][kk] = vb * (1.f / (1.f + __expf(-cp)));
        }
        __syncthreads();
        int Q = ct * 48 + q;
        float acc[Bb][4];
        #pragma unroll
        for (int b = 0; b < Bb; b++) { acc[b][0]=0.f; acc[b][1]=0.f; acc[b][2]=0.f; acc[b][3]=0.f; }
        const float4* wp = (const float4*)Wo + (size_t)(k0 + kg * 16) * 192 + Q;
        #pragma unroll
        for (int kk = 0; kk < 16; kk++) {
            float4 w = wp[(size_t)kk * 192];
            int ki = kg * 16 + kk;
            #pragma unroll
            for (int b = 0; b < Bb; b++) {
                float a = sa[b][ki];
                acc[b][0] += a * w.x; acc[b][1] += a * w.y;
                acc[b][2] += a * w.z; acc[b][3] += a * w.w;
            }
        }
        #pragma unroll
        for (int b = 0; b < Bb; b++)
            #pragma unroll
            for (int j = 0; j < 4; j++) {
                acc[b][j] += __shfl_xor_sync(0xffffffffu, acc[b][j], 1);
                acc[b][j] += __shfl_xor_sync(0xffffffffu, acc[b][j], 2);
            }
        if (kg == 0) {
            #pragma unroll
            for (int b = 0; b < Bb; b++)
                #pragma unroll
                for (int j = 0; j < 4; j++)
                    atomicAdd(&g_acc[S_YB + b * Cdim + 4 * Q + j], acc[b][j]);
        }
    }

    gbar();

    // ───── Phase 5: fused residual + LayerNorm (64 rows per block) ─────────
    {
        int b = g >> 4;
        __syncthreads();   // sa no longer needed; reuse smem
        for (int i = t; i < Cdim; i += NT) {
            smem[i]            = g_acc[S_YB + b * Cdim + i] + bo[i];  // w
            smem[Cdim + i]     = gamma[i];
            smem[2 * Cdim + i] = beta[i];
        }
        __syncthreads();
        const float4* wp = reinterpret_cast<const float4*>(smem);
        const float4* gp = reinterpret_cast<const float4*>(smem + Cdim);
        const float4* ep = reinterpret_cast<const float4*>(smem + 2 * Cdim);
        int w = t >> 5, lane = t & 31;
        int r_end = g * 64 + 64;
        for (int r = g * 64 + w; r < r_end; r += 6) {
            const float4* xp = reinterpret_cast<const float4*>(x + (size_t)r * Cdim);
            float4 v[6];
            float s = 0.f, qs = 0.f;
            #pragma unroll
            for (int i = 0; i < 6; i++) {
                int c = lane + 32 * i;
                float4 xv = xp[c], wv = wp[c];
                v[i].x = xv.x + wv.x; v[i].y = xv.y + wv.y;
                v[i].z = xv.z + wv.z; v[i].w = xv.w + wv.w;
                s  += v[i].x + v[i].y + v[i].z + v[i].w;
                qs += v[i].x*v[i].x + v[i].y*v[i].y + v[i].z*v[i].z + v[i].w*v[i].w;
            }
            #pragma unroll
            for (int o = 16; o; o >>= 1) {
                s  += __shfl_xor_sync(0xffffffffu, s, o);
                qs += __shfl_xor_sync(0xffffffffu, qs, o);
            }
            float mean = s * (1.0f / Cdim);
            float var = qs * (1.0f / Cdim) - mean * mean;
            float rstd = rsqrtf(var + 1e-5f);
            float4* op = reinterpret_cast<float4*>(out + (size_t)r * Cdim);
            #pragma unroll
            for (int i = 0; i < 6; i++) {
                int c = lane + 32 * i;
                float4 g4 = gp[c], e4 = ep[c], o4;
                o4.x = (v[i].x - mean) * rstd * g4.x + e4.x;
                o4.y = (v[i].y - mean) * rstd * g4.y + e4.y;
                o4.z = (v[i].z - mean) * rstd * g4.z + e4.z;
                o4.w = (v[i].w - mean) * rstd * g4.w + e4.w;
                op[c] = o4;
            }
        }
    }
}

extern "C" void kernel_launch(void* const* d_in, const int* in_sizes, int n_in,
                              void* d_out, int out_size) {
    const float* x     = (const float*)d_in[0];
    // d_in[1..4] = Wq, bq, Wk, bk — mathematically unused: k is constant over
    // sequence positions, so softmax is exactly uniform and attention output
    // equals mean(v) = gc@Wv + bv, independent of q/k.
    const float* Wv    = (const float*)d_in[5];
    const float* bv    = (const float*)d_in[6];
    const float* W1    = (const float*)d_in[7];
    const float* b1    = (const float*)d_in[8];
    const float* W2    = (const float*)d_in[9];
    const float* b2    = (const float*)d_in[10];
    const float* Wo    = (const float*)d_in[11];
    const float* bo    = (const float*)d_in[12];
    const float* gamma = (const float*)d_in[13];
    const float* beta  = (const float*)d_in[14];
    float* out = (float*)d_out;

    k_all<<<G, NT>>>(x, Wv, W1, W2, Wo, bv, b1, b2, bo, gamma, beta, out);
}

// round 8
// speedup vs baseline: 1.0081x; 1.0081x over previous
#include <cuda_runtime.h>

#define Cdim 768
#define CRdim 192
#define Bb 8
#define Nn 1024
#define CG 120            // chain grid

// gc accumulator (atomic; zeroed by k_chain after last use each call)
__device__ __align__(16) float g_gc[Bb * Cdim];
// other accumulators (zeroed by k_gc spare blocks each call)
#define S_VB 0
#define S_CA (Bb * Cdim)
#define S_YB (2 * Bb * Cdim)
#define S_H  (3 * Bb * Cdim)
#define S_ACC_N (3 * Bb * Cdim + Bb * CRdim)
__device__ __align__(16) float g_acc[S_ACC_N];
__device__ unsigned int g_cnt;
__device__ volatile unsigned int g_sense;

// Sense-reversing grid barrier — self-resetting, identical work every call.
__device__ __forceinline__ void gbar() {
    __syncthreads();
    if (threadIdx.x == 0) {
        unsigned s = g_sense;
        __threadfence();
        if (atomicAdd(&g_cnt, 1u) == CG - 1) {
            g_cnt = 0u;
            __threadfence();
            g_sense = s ^ 1u;
        } else {
            while (g_sense == s) __nanosleep(32);
        }
        __threadfence();
    }
    __syncthreads();
}

// ───────── K1: gc reduce (blocks 0..1023) + zero accumulators (1024..1031) ─
// 8 rows per block; 8 independent float4 loads per thread → MLP≈8.
__global__ void __launch_bounds__(192) k_gc(const float* __restrict__ x) {
    int t = threadIdx.x, g = blockIdx.x;
    if (g < 1024) {
        int b = g >> 7;                  // 128 blocks per batch
        int chunk = g & 127;             // 8-row chunk
        const float4* p = reinterpret_cast<const float4*>(x)
                        + (size_t)(b * Nn + chunk * 8) * (Cdim / 4) + t;
        float4 v0 = p[0 * (Cdim / 4)];
        float4 v1 = p[1 * (Cdim / 4)];
        float4 v2 = p[2 * (Cdim / 4)];
        float4 v3 = p[3 * (Cdim / 4)];
        float4 v4 = p[4 * (Cdim / 4)];
        float4 v5 = p[5 * (Cdim / 4)];
        float4 v6 = p[6 * (Cdim / 4)];
        float4 v7 = p[7 * (Cdim / 4)];
        float sx = ((v0.x + v1.x) + (v2.x + v3.x)) + ((v4.x + v5.x) + (v6.x + v7.x));
        float sy = ((v0.y + v1.y) + (v2.y + v3.y)) + ((v4.y + v5.y) + (v6.y + v7.y));
        float sz = ((v0.z + v1.z) + (v2.z + v3.z)) + ((v4.z + v5.z) + (v6.z + v7.z));
        float sw = ((v0.w + v1.w) + (v2.w + v3.w)) + ((v4.w + v5.w) + (v6.w + v7.w));
        float* gp = &g_gc[b * Cdim + 4 * t];
        const float inv = 1.0f / Nn;
        atomicAdd(gp + 0, sx * inv);
        atomicAdd(gp + 1, sy * inv);
        atomicAdd(gp + 2, sz * inv);
        atomicAdd(gp + 3, sw * inv);
    } else {
        for (int i = (g - 1024) * 192 + t; i < S_ACC_N; i += 8 * 192)
            g_acc[i] = 0.f;
    }
}

// ───────── K2: fused GEMM chain, 120 blocks × 192 threads ──────────────────
// Thread = (quad q8 = t>>3 of 24, k-lane kg = t&7 of 8, 8 k each; K-tile 64).
// Stage A (120 blk): vbar = gc@Wv, h = gc@W1   (atomic k-split)
// Stage B (24 blk):  ca_pre = relu(h+b1)@W2 ;  blocks 96..119 zero gc
// Stage C (96 blk):  ybar = ((vbar+bv)*sigmoid(ca+b2))@Wo
__global__ void __launch_bounds__(192) k_chain(const float* __restrict__ Wv,
                                               const float* __restrict__ W1,
                                               const float* __restrict__ W2,
                                               const float* __restrict__ Wo,
                                               const float* __restrict__ bv,
                                               const float* __restrict__ b1,
                                               const float* __restrict__ b2) {
    __shared__ float sa[Bb][64];
    int t = threadIdx.x, g = blockIdx.x;
    int q8 = t >> 3, kg = t & 7;

    // ---------------- Stage A ----------------
    {
        int ct = g / 12;                // 0..9   (col tile of 24 quads)
        int kt = g % 12;                // 0..11  (k tile of 64)
        int k0 = kt * 64;
        for (int i = t; i < Bb * 64; i += 192) {
            int b = i >> 6, kk = i & 63;
            sa[b][kk] = g_gc[b * Cdim + k0 + kk];
        }
        __syncthreads();
        int Q = ct * 24 + q8;           // 0..239 col-quad
        float acc[Bb][4];
        #pragma unroll
        for (int b = 0; b < Bb; b++) { acc[b][0]=0.f; acc[b][1]=0.f; acc[b][2]=0.f; acc[b][3]=0.f; }
        if (Q < 192) {
            const float4* wp = (const float4*)Wv + (size_t)(k0 + kg * 8) * 192 + Q;
            #pragma unroll
            for (int kk = 0; kk < 8; kk++) {
                float4 w = wp[(size_t)kk * 192];
                int ki = kg * 8 + kk;
                #pragma unroll
                for (int b = 0; b < Bb; b++) {
                    float a = sa[b][ki];
                    acc[b][0] += a * w.x; acc[b][1] += a * w.y;
                    acc[b][2] += a * w.z; acc[b][3] += a * w.w;
                }
            }
        } else {
            const float4* wp = (const float4*)W1 + (size_t)(k0 + kg * 8) * 48 + (Q - 192);
            #pragma unroll
            for (int kk = 0; kk < 8; kk++) {
                float4 w = wp[(size_t)kk * 48];
                int ki = kg * 8 + kk;
                #pragma unroll
                for (int b = 0; b < Bb; b++) {
                    float a = sa[b][ki];
                    acc[b][0] += a * w.x; acc[b][1] += a * w.y;
                    acc[b][2] += a * w.z; acc[b][3] += a * w.w;
                }
            }
        }
        #pragma unroll
        for (int b = 0; b < Bb; b++)
            #pragma unroll
            for (int j = 0; j < 4; j++) {
                acc[b][j] += __shfl_xor_sync(0xffffffffu, acc[b][j], 1);
                acc[b][j] += __shfl_xor_sync(0xffffffffu, acc[b][j], 2);
                acc[b][j] += __shfl_xor_sync(0xffffffffu, acc[b][j], 4);
            }
        if (kg == 0) {
            if (Q < 192) {
                #pragma unroll
                for (int b = 0; b < Bb; b++)
                    #pragma unroll
                    for (int j = 0; j < 4; j++)
                        atomicAdd(&g_acc[S_VB + b * Cdim + 4 * Q + j], acc[b][j]);
            } else {
                #pragma unroll
                for (int b = 0; b < Bb; b++)
                    #pragma unroll
                    for (int j = 0; j < 4; j++)
                        atomicAdd(&g_acc[S_H + b * CRdim + 4 * (Q - 192) + j], acc[b][j]);
            }
        }
    }

    gbar();

    // ---------------- Stage B (0..23) + gc re-zero (96..119) ---------------
    if (g < 24) {
        int ct = g & 7;                 // 0..7 (24-quad tile of 192)
        int kt = g >> 3;                // 0..2 (k tile of 64 over K=192)
        int k0 = kt * 64;
        for (int i = t; i < Bb * 64; i += 192) {
            int b = i >> 6, kk = i & 63;
            float v = g_acc[S_H + b * CRdim + k0 + kk] + b1[k0 + kk];
            sa[b][kk] = v > 0.f ? v : 0.f;
        }
        __syncthreads();
        int Q = ct * 24 + q8;
        float acc[Bb][4];
        #pragma unroll
        for (int b = 0; b < Bb; b++) { acc[b][0]=0.f; acc[b][1]=0.f; acc[b][2]=0.f; acc[b][3]=0.f; }
        const float4* wp = (const float4*)W2 + (size_t)(k0 + kg * 8) * 192 + Q;
        #pragma unroll
        for (int kk = 0; kk < 8; kk++) {
            float4 w = wp[(size_t)kk * 192];
            int ki = kg * 8 + kk;
            #pragma unroll
            for (int b = 0; b < Bb; b++) {
                float a = sa[b][ki];
                acc[b][0] += a * w.x; acc[b][1] += a * w.y;
                acc[b][2] += a * w.z; acc[b][3] += a * w.w;
            }
        }
        #pragma unroll
        for (int b = 0; b < Bb; b++)
            #pragma unroll
            for (int j = 0; j < 4; j++) {
                acc[b][j] += __shfl_xor_sync(0xffffffffu, acc[b][j], 1);
                acc[b][j] += __shfl_xor_sync(0xffffffffu, acc[b][j], 2);
                acc[b][j] += __shfl_xor_sync(0xffffffffu, acc[b][j], 4);
            }
        if (kg == 0) {
            #pragma unroll
            for (int b = 0; b < Bb; b++)
                #pragma unroll
                for (int j = 0; j < 4; j++)
                    atomicAdd(&g_acc[S_CA + b * Cdim + 4 * Q + j], acc[b][j]);
        }
    } else if (g >= 96) {
        // gc fully consumed in Stage A; zero it for the next call.
        for (int i = (g - 96) * 192 + t; i < Bb * Cdim; i += 24 * 192)
            g_gc[i] = 0.f;
    }

    gbar();

    // ---------------- Stage C (0..95) ----------------
    if (g < 96) {
        int ct = g & 7;                 // 0..7
        int kt = g >> 3;                // 0..11
        int k0 = kt * 64;
        for (int i = t; i < Bb * 64; i += 192) {
            int b = i >> 6, kk = i & 63;
            int k = k0 + kk;
            float vb = g_acc[S_VB + b * Cdim + k] + bv[k];
            float cp = g_acc[S_CA + b * Cdim + k] + b2[k];
            sa[b][kk] = vb * (1.f / (1.f + __expf(-cp)));
        }
        __syncthreads();
        int Q = ct * 24 + q8;
        float acc[Bb][4];
        #pragma unroll
        for (int b = 0; b < Bb; b++) { acc[b][0]=0.f; acc[b][1]=0.f; acc[b][2]=0.f; acc[b][3]=0.f; }
        const float4* wp = (const float4*)Wo + (size_t)(k0 + kg * 8) * 192 + Q;
        #pragma unroll
        for (int kk = 0; kk < 8; kk++) {
            float4 w = wp[(size_t)kk * 192];
            int ki = kg * 8 + kk;
            #pragma unroll
            for (int b = 0; b < Bb; b++) {
                float a = sa[b][ki];
                acc[b][0] += a * w.x; acc[b][1] += a * w.y;
                acc[b][2] += a * w.z; acc[b][3] += a * w.w;
            }
        }
        #pragma unroll
        for (int b = 0; b < Bb; b++)
            #pragma unroll
            for (int j = 0; j < 4; j++) {
                acc[b][j] += __shfl_xor_sync(0xffffffffu, acc[b][j], 1);
                acc[b][j] += __shfl_xor_sync(0xffffffffu, acc[b][j], 2);
                acc[b][j] += __shfl_xor_sync(0xffffffffu, acc[b][j], 4);
            }
        if (kg == 0) {
            #pragma unroll
            for (int b = 0; b < Bb; b++)
                #pragma unroll
                for (int j = 0; j < 4; j++)
                    atomicAdd(&g_acc[S_YB + b * Cdim + 4 * Q + j], acc[b][j]);
        }
    }
}

// ───────── K3: warp-per-row fused residual + LayerNorm ─────────────────────
__global__ void __launch_bounds__(192) k_ln(const float* __restrict__ x,
                                            const float* __restrict__ bo,
                                            const float* __restrict__ gamma,
                                            const float* __restrict__ beta,
                                            float* __restrict__ out) {
    int row = blockIdx.x * 6 + (threadIdx.x >> 5);
    if (row >= Bb * Nn) return;
    int lane = threadIdx.x & 31;
    int b = row >> 10;
    const float4* xp = reinterpret_cast<const float4*>(x + (size_t)row * Cdim);
    const float4* yp = reinterpret_cast<const float4*>(&g_acc[S_YB + b * Cdim]);
    const float4* bp = reinterpret_cast<const float4*>(bo);
    float4 v[6];
    float s = 0.f, qs = 0.f;
    #pragma unroll
    for (int i = 0; i < 6; i++) {
        int c = lane + 32 * i;
        float4 xv = xp[c], yv = yp[c], b4 = bp[c];
        v[i].x = xv.x + yv.x + b4.x;
        v[i].y = xv.y + yv.y + b4.y;
        v[i].z = xv.z + yv.z + b4.z;
        v[i].w = xv.w + yv.w + b4.w;
        s  += v[i].x + v[i].y + v[i].z + v[i].w;
        qs += v[i].x*v[i].x + v[i].y*v[i].y + v[i].z*v[i].z + v[i].w*v[i].w;
    }
    #pragma unroll
    for (int o = 16; o; o >>= 1) {
        s  += __shfl_xor_sync(0xffffffffu, s, o);
        qs += __shfl_xor_sync(0xffffffffu, qs, o);
    }
    float mean = s * (1.0f / Cdim);
    float var = qs * (1.0f / Cdim) - mean * mean;
    float rstd = rsqrtf(var + 1e-5f);
    const float4* gp = reinterpret_cast<const float4*>(gamma);
    const float4* ep = reinterpret_cast<const float4*>(beta);
    float4* op = reinterpret_cast<float4*>(out + (size_t)row * Cdim);
    #pragma unroll
    for (int i = 0; i < 6; i++) {
        int c = lane + 32 * i;
        float4 g4 = gp[c], e4 = ep[c], o4;
        o4.x = (v[i].x - mean) * rstd * g4.x + e4.x;
        o4.y = (v[i].y - mean) * rstd * g4.y + e4.y;
        o4.z = (v[i].z - mean) * rstd * g4.z + e4.z;
        o4.w = (v[i].w - mean) * rstd * g4.w + e4.w;
        op[c] = o4;
    }
}

extern "C" void kernel_launch(void* const* d_in, const int* in_sizes, int n_in,
                              void* d_out, int out_size) {
    const float* x     = (const float*)d_in[0];
    // d_in[1..4] = Wq, bq, Wk, bk — mathematically unused: k is constant over
    // sequence positions, so softmax is exactly uniform and attention output
    // equals mean(v) = gc@Wv + bv, independent of q/k.
    const float* Wv    = (const float*)d_in[5];
    const float* bv    = (const float*)d_in[6];
    const float* W1    = (const float*)d_in[7];
    const float* b1    = (const float*)d_in[8];
    const float* W2    = (const float*)d_in[9];
    const float* b2    = (const float*)d_in[10];
    const float* Wo    = (const float*)d_in[11];
    const float* bo    = (const float*)d_in[12];
    const float* gamma = (const float*)d_in[13];
    const float* beta  = (const float*)d_in[14];
    float* out = (float*)d_out;

    k_gc<<<1032, 192>>>(x);
    k_chain<<<CG, 192>>>(Wv, W1, W2, Wo, bv, b1, b2);
    k_ln<<<(Bb * Nn + 5) / 6, 192>>>(x, bo, gamma, beta, out);
}

// round 9
// speedup vs baseline: 1.0897x; 1.0809x over previous
#include <cuda_runtime.h>

#define Cdim 768
#define CRdim 192
#define Bb 8
#define Nn 1024
#define CG 120            // chain grid

// gc accumulator (atomic; zeroed by k_chain after last use each call)
__device__ __align__(16) float g_gc[Bb * Cdim];
// other accumulators (zeroed by k_gc spare blocks each call)
#define S_VB 0
#define S_CA (Bb * Cdim)
#define S_YB (2 * Bb * Cdim)
#define S_H  (3 * Bb * Cdim)
#define S_ACC_N (3 * Bb * Cdim + Bb * CRdim)
__device__ __align__(16) float g_acc[S_ACC_N];
__device__ unsigned int g_cnt;
__device__ volatile unsigned int g_sense;

// Sense-reversing grid barrier — self-resetting, identical work every call.
__device__ __forceinline__ void gbar() {
    __syncthreads();
    if (threadIdx.x == 0) {
        unsigned s = g_sense;
        __threadfence();
        if (atomicAdd(&g_cnt, 1u) == CG - 1) {
            g_cnt = 0u;
            __threadfence();
            g_sense = s ^ 1u;
        } else {
            while (g_sense == s) __nanosleep(32);
        }
        __threadfence();
    }
    __syncthreads();
}

// ───────── K1: gc reduce (blocks 0..511, 16 rows each) + zero g_acc ────────
__global__ void __launch_bounds__(192) k_gc(const float* __restrict__ x) {
    int t = threadIdx.x, g = blockIdx.x;
    if (g < 512) {
        int b = g >> 6;                  // batch
        int chunk = g & 63;              // 16-row chunk
        const float4* p = reinterpret_cast<const float4*>(x)
                        + (size_t)(b * Nn + chunk * 16) * (Cdim / 4) + t;
        float4 s = make_float4(0.f, 0.f, 0.f, 0.f);
        #pragma unroll
        for (int n = 0; n < 16; n++) {
            float4 v = p[(size_t)n * (Cdim / 4)];
            s.x += v.x; s.y += v.y; s.z += v.z; s.w += v.w;
        }
        float* gp = &g_gc[b * Cdim + 4 * t];
        const float inv = 1.0f / Nn;
        atomicAdd(gp + 0, s.x * inv);
        atomicAdd(gp + 1, s.y * inv);
        atomicAdd(gp + 2, s.z * inv);
        atomicAdd(gp + 3, s.w * inv);
    } else {
        for (int i = (g - 512) * 192 + t; i < S_ACC_N; i += 8 * 192)
            g_acc[i] = 0.f;
    }
}

// ───────── K2: fused GEMM chain, 120 blocks × 192 threads ──────────────────
// Thread = (quad q8 = t>>3 of 24, k-lane kg = t&7 of 8, 8 k each; K-tile 64).
// Stage A (120 blk): vbar = gc@Wv, h = gc@W1   (atomic k-split)
// Stage B (24 blk):  ca_pre = relu(h+b1)@W2 ;  blocks 96..119 zero gc
// Stage C (96 blk):  ybar = ((vbar+bv)*sigmoid(ca+b2))@Wo
__global__ void __launch_bounds__(192) k_chain(const float* __restrict__ Wv,
                                               const float* __restrict__ W1,
                                               const float* __restrict__ W2,
                                               const float* __restrict__ Wo,
                                               const float* __restrict__ bv,
                                               const float* __restrict__ b1,
                                               const float* __restrict__ b2) {
    __shared__ float sa[Bb][64];
    int t = threadIdx.x, g = blockIdx.x;
    int q8 = t >> 3, kg = t & 7;

    // ---------------- Stage A ----------------
    {
        int ct = g / 12;                // 0..9   (col tile of 24 quads)
        int kt = g % 12;                // 0..11  (k tile of 64)
        int k0 = kt * 64;
        for (int i = t; i < Bb * 64; i += 192) {
            int b = i >> 6, kk = i & 63;
            sa[b][kk] = g_gc[b * Cdim + k0 + kk];
        }
        __syncthreads();
        int Q = ct * 24 + q8;           // 0..239 col-quad
        float acc[Bb][4];
        #pragma unroll
        for (int b = 0; b < Bb; b++) { acc[b][0]=0.f; acc[b][1]=0.f; acc[b][2]=0.f; acc[b][3]=0.f; }
        if (Q < 192) {
            const float4* wp = (const float4*)Wv + (size_t)(k0 + kg * 8) * 192 + Q;
            #pragma unroll
            for (int kk = 0; kk < 8; kk++) {
                float4 w = wp[(size_t)kk * 192];
                int ki = kg * 8 + kk;
                #pragma unroll
                for (int b = 0; b < Bb; b++) {
                    float a = sa[b][ki];
                    acc[b][0] += a * w.x; acc[b][1] += a * w.y;
                    acc[b][2] += a * w.z; acc[b][3] += a * w.w;
                }
            }
        } else {
            const float4* wp = (const float4*)W1 + (size_t)(k0 + kg * 8) * 48 + (Q - 192);
            #pragma unroll
            for (int kk = 0; kk < 8; kk++) {
                float4 w = wp[(size_t)kk * 48];
                int ki = kg * 8 + kk;
                #pragma unroll
                for (int b = 0; b < Bb; b++) {
                    float a = sa[b][ki];
                    acc[b][0] += a * w.x; acc[b][1] += a * w.y;
                    acc[b][2] += a * w.z; acc[b][3] += a * w.w;
                }
            }
        }
        #pragma unroll
        for (int b = 0; b < Bb; b++)
            #pragma unroll
            for (int j = 0; j < 4; j++) {
                acc[b][j] += __shfl_xor_sync(0xffffffffu, acc[b][j], 1);
                acc[b][j] += __shfl_xor_sync(0xffffffffu, acc[b][j], 2);
                acc[b][j] += __shfl_xor_sync(0xffffffffu, acc[b][j], 4);
            }
        if (kg == 0) {
            if (Q < 192) {
                #pragma unroll
                for (int b = 0; b < Bb; b++)
                    #pragma unroll
                    for (int j = 0; j < 4; j++)
                        atomicAdd(&g_acc[S_VB + b * Cdim + 4 * Q + j], acc[b][j]);
            } else {
                #pragma unroll
                for (int b = 0; b < Bb; b++)
                    #pragma unroll
                    for (int j = 0; j < 4; j++)
                        atomicAdd(&g_acc[S_H + b * CRdim + 4 * (Q - 192) + j], acc[b][j]);
            }
        }
    }

    gbar();

    // ---------------- Stage B (0..23) + gc re-zero (96..119) ---------------
    if (g < 24) {
        int ct = g & 7;                 // 0..7 (24-quad tile of 192)
        int kt = g >> 3;                // 0..2 (k tile of 64 over K=192)
        int k0 = kt * 64;
        for (int i = t; i < Bb * 64; i += 192) {
            int b = i >> 6, kk = i & 63;
            float v = g_acc[S_H + b * CRdim + k0 + kk] + b1[k0 + kk];
            sa[b][kk] = v > 0.f ? v : 0.f;
        }
        __syncthreads();
        int Q = ct * 24 + q8;
        float acc[Bb][4];
        #pragma unroll
        for (int b = 0; b < Bb; b++) { acc[b][0]=0.f; acc[b][1]=0.f; acc[b][2]=0.f; acc[b][3]=0.f; }
        const float4* wp = (const float4*)W2 + (size_t)(k0 + kg * 8) * 192 + Q;
        #pragma unroll
        for (int kk = 0; kk < 8; kk++) {
            float4 w = wp[(size_t)kk * 192];
            int ki = kg * 8 + kk;
            #pragma unroll
            for (int b = 0; b < Bb; b++) {
                float a = sa[b][ki];
                acc[b][0] += a * w.x; acc[b][1] += a * w.y;
                acc[b][2] += a * w.z; acc[b][3] += a * w.w;
            }
        }
        #pragma unroll
        for (int b = 0; b < Bb; b++)
            #pragma unroll
            for (int j = 0; j < 4; j++) {
                acc[b][j] += __shfl_xor_sync(0xffffffffu, acc[b][j], 1);
                acc[b][j] += __shfl_xor_sync(0xffffffffu, acc[b][j], 2);
                acc[b][j] += __shfl_xor_sync(0xffffffffu, acc[b][j], 4);
            }
        if (kg == 0) {
            #pragma unroll
            for (int b = 0; b < Bb; b++)
                #pragma unroll
                for (int j = 0; j < 4; j++)
                    atomicAdd(&g_acc[S_CA + b * Cdim + 4 * Q + j], acc[b][j]);
        }
    } else if (g >= 96) {
        // gc fully consumed in Stage A; zero it for the next call.
        for (int i = (g - 96) * 192 + t; i < Bb * Cdim; i += 24 * 192)
            g_gc[i] = 0.f;
    }

    gbar();

    // ---------------- Stage C (0..95) ----------------
    if (g < 96) {
        int ct = g & 7;                 // 0..7
        int kt = g >> 3;                // 0..11
        int k0 = kt * 64;
        for (int i = t; i < Bb * 64; i += 192) {
            int b = i >> 6, kk = i & 63;
            int k = k0 + kk;
            float vb = g_acc[S_VB + b * Cdim + k] + bv[k];
            float cp = g_acc[S_CA + b * Cdim + k] + b2[k];
            sa[b][kk] = vb * (1.f / (1.f + __expf(-cp)));
        }
        __syncthreads();
        int Q = ct * 24 + q8;
        float acc[Bb][4];
        #pragma unroll
        for (int b = 0; b < Bb; b++) { acc[b][0]=0.f; acc[b][1]=0.f; acc[b][2]=0.f; acc[b][3]=0.f; }
        const float4* wp = (const float4*)Wo + (size_t)(k0 + kg * 8) * 192 + Q;
        #pragma unroll
        for (int kk = 0; kk < 8; kk++) {
            float4 w = wp[(size_t)kk * 192];
            int ki = kg * 8 + kk;
            #pragma unroll
            for (int b = 0; b < Bb; b++) {
                float a = sa[b][ki];
                acc[b][0] += a * w.x; acc[b][1] += a * w.y;
                acc[b][2] += a * w.z; acc[b][3] += a * w.w;
            }
        }
        #pragma unroll
        for (int b = 0; b < Bb; b++)
            #pragma unroll
            for (int j = 0; j < 4; j++) {
                acc[b][j] += __shfl_xor_sync(0xffffffffu, acc[b][j], 1);
                acc[b][j] += __shfl_xor_sync(0xffffffffu, acc[b][j], 2);
                acc[b][j] += __shfl_xor_sync(0xffffffffu, acc[b][j], 4);
            }
        if (kg == 0) {
            #pragma unroll
            for (int b = 0; b < Bb; b++)
                #pragma unroll
                for (int j = 0; j < 4; j++)
                    atomicAdd(&g_acc[S_YB + b * Cdim + 4 * Q + j], acc[b][j]);
        }
    }
}

// ───────── K3: fused residual + LN, smem-cached per-batch vectors ──────────
// 256 blocks × 256 threads. Block = 32 consecutive rows (same batch since
// 1024 % 32 == 0). w = ybar[b]+bo, gamma, beta loaded ONCE per block into
// smem — removes ~100 MB of per-row global re-reads vs the old k_ln.
__global__ void __launch_bounds__(256) k_ln(const float* __restrict__ x,
                                            const float* __restrict__ bo,
                                            const float* __restrict__ gamma,
                                            const float* __restrict__ beta,
                                            float* __restrict__ out) {
    __shared__ float sw[Cdim], sg[Cdim], sb[Cdim];
    int g = blockIdx.x;                 // 0..255
    int t = threadIdx.x;
    int b = g >> 5;                     // 32 blocks per batch
    for (int i = t; i < Cdim; i += 256) {
        sw[i] = g_acc[S_YB + b * Cdim + i] + bo[i];
        sg[i] = gamma[i];
        sb[i] = beta[i];
    }
    __syncthreads();
    const float4* wp = reinterpret_cast<const float4*>(sw);
    const float4* gp = reinterpret_cast<const float4*>(sg);
    const float4* ep = reinterpret_cast<const float4*>(sb);
    int w = t >> 5, lane = t & 31;
    int row0 = g * 32;
    #pragma unroll
    for (int rr = 0; rr < 4; rr++) {
        int r = row0 + w + rr * 8;
        const float4* xp = reinterpret_cast<const float4*>(x + (size_t)r * Cdim);
        float4 v[6];
        float s = 0.f, qs = 0.f;
        #pragma unroll
        for (int i = 0; i < 6; i++) {
            int c = lane + 32 * i;
            float4 xv = xp[c], wv = wp[c];
            v[i].x = xv.x + wv.x; v[i].y = xv.y + wv.y;
            v[i].z = xv.z + wv.z; v[i].w = xv.w + wv.w;
            s  += v[i].x + v[i].y + v[i].z + v[i].w;
            qs += v[i].x*v[i].x + v[i].y*v[i].y + v[i].z*v[i].z + v[i].w*v[i].w;
        }
        #pragma unroll
        for (int o = 16; o; o >>= 1) {
            s  += __shfl_xor_sync(0xffffffffu, s, o);
            qs += __shfl_xor_sync(0xffffffffu, qs, o);
        }
        float mean = s * (1.0f / Cdim);
        float var = qs * (1.0f / Cdim) - mean * mean;
        float rstd = rsqrtf(var + 1e-5f);
        float4* op = reinterpret_cast<float4*>(out + (size_t)r * Cdim);
        #pragma unroll
        for (int i = 0; i < 6; i++) {
            int c = lane + 32 * i;
            float4 g4 = gp[c], e4 = ep[c], o4;
            o4.x = (v[i].x - mean) * rstd * g4.x + e4.x;
            o4.y = (v[i].y - mean) * rstd * g4.y + e4.y;
            o4.z = (v[i].z - mean) * rstd * g4.z + e4.z;
            o4.w = (v[i].w - mean) * rstd * g4.w + e4.w;
            op[c] = o4;
        }
    }
}

extern "C" void kernel_launch(void* const* d_in, const int* in_sizes, int n_in,
                              void* d_out, int out_size) {
    const float* x     = (const float*)d_in[0];
    // d_in[1..4] = Wq, bq, Wk, bk — mathematically unused: k is constant over
    // sequence positions, so softmax is exactly uniform and attention output
    // equals mean(v) = gc@Wv + bv, independent of q/k.
    const float* Wv    = (const float*)d_in[5];
    const float* bv    = (const float*)d_in[6];
    const float* W1    = (const float*)d_in[7];
    const float* b1    = (const float*)d_in[8];
    const float* W2    = (const float*)d_in[9];
    const float* b2    = (const float*)d_in[10];
    const float* Wo    = (const float*)d_in[11];
    const float* bo    = (const float*)d_in[12];
    const float* gamma = (const float*)d_in[13];
    const float* beta  = (const float*)d_in[14];
    float* out = (float*)d_out;

    k_gc<<<520, 192>>>(x);
    k_chain<<<CG, 192>>>(Wv, W1, W2, Wo, bv, b1, b2);
    k_ln<<<256, 256>>>(x, bo, gamma, beta, out);
}

// round 13
// speedup vs baseline: 1.1634x; 1.0676x over previous
#include <cuda_runtime.h>

#define Cdim 768
#define CRdim 192
#define Bb 8
#define Nn 1024

// gc accumulator (atomic; zeroed by k_gemm2's spare blocks each call)
__device__ __align__(16) float g_gc[Bb * Cdim];
// other accumulators (zeroed by k_gc's spare blocks each call)
#define S_VB 0
#define S_CA (Bb * Cdim)
#define S_YB (2 * Bb * Cdim)
#define S_H  (3 * Bb * Cdim)
#define S_ACC_N (3 * Bb * Cdim + Bb * CRdim)
__device__ __align__(16) float g_acc[S_ACC_N];

// ───────── K1: gc reduce (blocks 0..511, 16 rows each) + zero g_acc ────────
__global__ void __launch_bounds__(192) k_gc(const float* __restrict__ x) {
    int t = threadIdx.x, g = blockIdx.x;
    if (g < 512) {
        int b = g >> 6;                  // batch
        int chunk = g & 63;              // 16-row chunk
        const float4* p = reinterpret_cast<const float4*>(x)
                        + (size_t)(b * Nn + chunk * 16) * (Cdim / 4) + t;
        float4 s = make_float4(0.f, 0.f, 0.f, 0.f);
        #pragma unroll
        for (int n = 0; n < 16; n++) {
            float4 v = p[(size_t)n * (Cdim / 4)];
            s.x += v.x; s.y += v.y; s.z += v.z; s.w += v.w;
        }
        float* gp = &g_gc[b * Cdim + 4 * t];
        const float inv = 1.0f / Nn;
        atomicAdd(gp + 0, s.x * inv);
        atomicAdd(gp + 1, s.y * inv);
        atomicAdd(gp + 2, s.z * inv);
        atomicAdd(gp + 3, s.w * inv);
    } else {
        for (int i = (g - 512) * 192 + t; i < S_ACC_N; i += 8 * 192)
            g_acc[i] = 0.f;
    }
}

// ───────── K2: vbar = gc@Wv, h = gc@W1   (atomic k-split) ──────────────────
// 120 blocks × 192 threads. Thread = (quad q8 = t>>3 of 24, k-lane kg = t&7).
__global__ void __launch_bounds__(192) k_gemm1(const float* __restrict__ Wv,
                                               const float* __restrict__ W1) {
    __shared__ float sa[Bb][64];
    int t = threadIdx.x, g = blockIdx.x;
    int q8 = t >> 3, kg = t & 7;
    int ct = g / 12;                // 0..9   (col tile of 24 quads)
    int kt = g % 12;                // 0..11  (k tile of 64)
    int k0 = kt * 64;
    for (int i = t; i < Bb * 64; i += 192) {
        int b = i >> 6, kk = i & 63;
        sa[b][kk] = g_gc[b * Cdim + k0 + kk];
    }
    __syncthreads();
    int Q = ct * 24 + q8;           // 0..239 col-quad
    float acc[Bb][4];
    #pragma unroll
    for (int b = 0; b < Bb; b++) { acc[b][0]=0.f; acc[b][1]=0.f; acc[b][2]=0.f; acc[b][3]=0.f; }
    if (Q < 192) {
        const float4* wp = (const float4*)Wv + (size_t)(k0 + kg * 8) * 192 + Q;
        #pragma unroll
        for (int kk = 0; kk < 8; kk++) {
            float4 w = wp[(size_t)kk * 192];
            int ki = kg * 8 + kk;
            #pragma unroll
            for (int b = 0; b < Bb; b++) {
                float a = sa[b][ki];
                acc[b][0] += a * w.x; acc[b][1] += a * w.y;
                acc[b][2] += a * w.z; acc[b][3] += a * w.w;
            }
        }
    } else {
        const float4* wp = (const float4*)W1 + (size_t)(k0 + kg * 8) * 48 + (Q - 192);
        #pragma unroll
        for (int kk = 0; kk < 8; kk++) {
            float4 w = wp[(size_t)kk * 48];
            int ki = kg * 8 + kk;
            #pragma unroll
            for (int b = 0; b < Bb; b++) {
                float a = sa[b][ki];
                acc[b][0] += a * w.x; acc[b][1] += a * w.y;
                acc[b][2] += a * w.z; acc[b][3] += a * w.w;
            }
        }
    }
    #pragma unroll
    for (int b = 0; b < Bb; b++)
        #pragma unroll
        for (int j = 0; j < 4; j++) {
            acc[b][j] += __shfl_xor_sync(0xffffffffu, acc[b][j], 1);
            acc[b][j] += __shfl_xor_sync(0xffffffffu, acc[b][j], 2);
            acc[b][j] += __shfl_xor_sync(0xffffffffu, acc[b][j], 4);
        }
    if (kg == 0) {
        if (Q < 192) {
            #pragma unroll
            for (int b = 0; b < Bb; b++)
                #pragma unroll
                for (int j = 0; j < 4; j++)
                    atomicAdd(&g_acc[S_VB + b * Cdim + 4 * Q + j], acc[b][j]);
        } else {
            #pragma unroll
            for (int b = 0; b < Bb; b++)
                #pragma unroll
                for (int j = 0; j < 4; j++)
                    atomicAdd(&g_acc[S_H + b * CRdim + 4 * (Q - 192) + j], acc[b][j]);
        }
    }
}

// ───────── K3: ca_pre = relu(h+b1)@W2 (blocks 0..23) + gc re-zero (24..47) ─
__global__ void __launch_bounds__(192) k_gemm2(const float* __restrict__ W2,
                                               const float* __restrict__ b1) {
    __shared__ float sa[Bb][64];
    int t = threadIdx.x, g = blockIdx.x;
    int q8 = t >> 3, kg = t & 7;
    if (g < 24) {
        int ct = g & 7;                 // 0..7 (24-quad tile of 192)
        int kt = g >> 3;                // 0..2 (k tile of 64 over K=192)
        int k0 = kt * 64;
        for (int i = t; i < Bb * 64; i += 192) {
            int b = i >> 6, kk = i & 63;
            float v = g_acc[S_H + b * CRdim + k0 + kk] + b1[k0 + kk];
            sa[b][kk] = v > 0.f ? v : 0.f;
        }
        __syncthreads();
        int Q = ct * 24 + q8;
        float acc[Bb][4];
        #pragma unroll
        for (int b = 0; b < Bb; b++) { acc[b][0]=0.f; acc[b][1]=0.f; acc[b][2]=0.f; acc[b][3]=0.f; }
        const float4* wp = (const float4*)W2 + (size_t)(k0 + kg * 8) * 192 + Q;
        #pragma unroll
        for (int kk = 0; kk < 8; kk++) {
            float4 w = wp[(size_t)kk * 192];
            int ki = kg * 8 + kk;
            #pragma unroll
            for (int b = 0; b < Bb; b++) {
                float a = sa[b][ki];
                acc[b][0] += a * w.x; acc[b][1] += a * w.y;
                acc[b][2] += a * w.z; acc[b][3] += a * w.w;
            }
        }
        #pragma unroll
        for (int b = 0; b < Bb; b++)
            #pragma unroll
            for (int j = 0; j < 4; j++) {
                acc[b][j] += __shfl_xor_sync(0xffffffffu, acc[b][j], 1);
                acc[b][j] += __shfl_xor_sync(0xffffffffu, acc[b][j], 2);
                acc[b][j] += __shfl_xor_sync(0xffffffffu, acc[b][j], 4);
            }
        if (kg == 0) {
            #pragma unroll
            for (int b = 0; b < Bb; b++)
                #pragma unroll
                for (int j = 0; j < 4; j++)
                    atomicAdd(&g_acc[S_CA + b * Cdim + 4 * Q + j], acc[b][j]);
        }
    } else {
        // gc fully consumed by k_gemm1 (previous kernel); zero for next call.
        for (int i = (g - 24) * 192 + t; i < Bb * Cdim; i += 24 * 192)
            g_gc[i] = 0.f;
    }
}

// ───────── K4: ybar = ((vbar+bv)*sigmoid(ca+b2))@Wo  (96 blocks) ───────────
__global__ void __launch_bounds__(192) k_gemm3(const float* __restrict__ Wo,
                                               const float* __restrict__ bv,
                                               const float* __restrict__ b2) {
    __shared__ float sa[Bb][64];
    int t = threadIdx.x, g = blockIdx.x;
    int q8 = t >> 3, kg = t & 7;
    int ct = g & 7;                 // 0..7
    int kt = g >> 3;                // 0..11
    int k0 = kt * 64;
    for (int i = t; i < Bb * 64; i += 192) {
        int b = i >> 6, kk = i & 63;
        int k = k0 + kk;
        float vb = g_acc[S_VB + b * Cdim + k] + bv[k];
        float cp = g_acc[S_CA + b * Cdim + k] + b2[k];
        sa[b][kk] = vb * (1.f / (1.f + __expf(-cp)));
    }
    __syncthreads();
    int Q = ct * 24 + q8;
    float acc[Bb][4];
    #pragma unroll
    for (int b = 0; b < Bb; b++) { acc[b][0]=0.f; acc[b][1]=0.f; acc[b][2]=0.f; acc[b][3]=0.f; }
    const float4* wp = (const float4*)Wo + (size_t)(k0 + kg * 8) * 192 + Q;
    #pragma unroll
    for (int kk = 0; kk < 8; kk++) {
        float4 w = wp[(size_t)kk * 192];
        int ki = kg * 8 + kk;
        #pragma unroll
        for (int b = 0; b < Bb; b++) {
            float a = sa[b][ki];
            acc[b][0] += a * w.x; acc[b][1] += a * w.y;
            acc[b][2] += a * w.z; acc[b][3] += a * w.w;
        }
    }
    #pragma unroll
    for (int b = 0; b < Bb; b++)
        #pragma unroll
        for (int j = 0; j < 4; j++) {
            acc[b][j] += __shfl_xor_sync(0xffffffffu, acc[b][j], 1);
            acc[b][j] += __shfl_xor_sync(0xffffffffu, acc[b][j], 2);
            acc[b][j] += __shfl_xor_sync(0xffffffffu, acc[b][j], 4);
        }
    if (kg == 0) {
        #pragma unroll
        for (int b = 0; b < Bb; b++)
            #pragma unroll
            for (int j = 0; j < 4; j++)
                atomicAdd(&g_acc[S_YB + b * Cdim + 4 * Q + j], acc[b][j]);
    }
}

// ───────── K5: fused residual + LN, smem-cached per-batch vectors ──────────
// 256 blocks × 256 threads. Block = 32 consecutive rows (same batch since
// 1024 % 32 == 0). w = ybar[b]+bo, gamma, beta loaded ONCE per block into
// smem — removes ~100 MB of per-row global re-reads vs the warp-per-row k_ln.
__global__ void __launch_bounds__(256) k_ln(const float* __restrict__ x,
                                            const float* __restrict__ bo,
                                            const float* __restrict__ gamma,
                                            const float* __restrict__ beta,
                                            float* __restrict__ out) {
    __shared__ float sw[Cdim], sg[Cdim], sb[Cdim];
    int g = blockIdx.x;                 // 0..255
    int t = threadIdx.x;
    int b = g >> 5;                     // 32 blocks per batch
    for (int i = t; i < Cdim; i += 256) {
        sw[i] = g_acc[S_YB + b * Cdim + i] + bo[i];
        sg[i] = gamma[i];
        sb[i] = beta[i];
    }
    __syncthreads();
    const float4* wp = reinterpret_cast<const float4*>(sw);
    const float4* gp = reinterpret_cast<const float4*>(sg);
    const float4* ep = reinterpret_cast<const float4*>(sb);
    int w = t >> 5, lane = t & 31;
    int row0 = g * 32;
    #pragma unroll
    for (int rr = 0; rr < 4; rr++) {
        int r = row0 + w + rr * 8;
        const float4* xp = reinterpret_cast<const float4*>(x + (size_t)r * Cdim);
        float4 v[6];
        float s = 0.f, qs = 0.f;
        #pragma unroll
        for (int i = 0; i < 6; i++) {
            int c = lane + 32 * i;
            float4 xv = xp[c], wv = wp[c];
            v[i].x = xv.x + wv.x; v[i].y = xv.y + wv.y;
            v[i].z = xv.z + wv.z; v[i].w = xv.w + wv.w;
            s  += v[i].x + v[i].y + v[i].z + v[i].w;
            qs += v[i].x*v[i].x + v[i].y*v[i].y + v[i].z*v[i].z + v[i].w*v[i].w;
        }
        #pragma unroll
        for (int o = 16; o; o >>= 1) {
            s  += __shfl_xor_sync(0xffffffffu, s, o);
            qs += __shfl_xor_sync(0xffffffffu, qs, o);
        }
        float mean = s * (1.0f / Cdim);
        float var = qs * (1.0f / Cdim) - mean * mean;
        float rstd = rsqrtf(var + 1e-5f);
        float4* op = reinterpret_cast<float4*>(out + (size_t)r * Cdim);
        #pragma unroll
        for (int i = 0; i < 6; i++) {
            int c = lane + 32 * i;
            float4 g4 = gp[c], e4 = ep[c], o4;
            o4.x = (v[i].x - mean) * rstd * g4.x + e4.x;
            o4.y = (v[i].y - mean) * rstd * g4.y + e4.y;
            o4.z = (v[i].z - mean) * rstd * g4.z + e4.z;
            o4.w = (v[i].w - mean) * rstd * g4.w + e4.w;
            op[c] = o4;
        }
    }
}

extern "C" void kernel_launch(void* const* d_in, const int* in_sizes, int n_in,
                              void* d_out, int out_size) {
    const float* x     = (const float*)d_in[0];
    // d_in[1..4] = Wq, bq, Wk, bk — mathematically unused: k is constant over
    // sequence positions, so softmax is exactly uniform and attention output
    // equals mean(v) = gc@Wv + bv, independent of q/k.
    const float* Wv    = (const float*)d_in[5];
    const float* bv    = (const float*)d_in[6];
    const float* W1    = (const float*)d_in[7];
    const float* b1    = (const float*)d_in[8];
    const float* W2    = (const float*)d_in[9];
    const float* b2    = (const float*)d_in[10];
    const float* Wo    = (const float*)d_in[11];
    const float* bo    = (const float*)d_in[12];
    const float* gamma = (const float*)d_in[13];
    const float* beta  = (const float*)d_in[14];
    float* out = (float*)d_out;

    k_gc<<<520, 192>>>(x);
    k_gemm1<<<120, 192>>>(Wv, W1);
    k_gemm2<<<48, 192>>>(W2, b1);     // 24 GEMM blocks + 24 gc-zero blocks
    k_gemm3<<<96, 192>>>(Wo, bv, b2);
    k_ln<<<256, 256>>>(x, bo, gamma, beta, out);
}